// round 6
// baseline (speedup 1.0000x reference)
#include <cuda_runtime.h>
#include <cuda_bf16.h>
#include <cstdint>

// LightGCN 2-hop smoothing, pull-based SpMM over on-the-fly CSR,
// bf16 gather payloads with pre-folded dis[] weights, fp32 accumulation.
// out = (2*x0 + 2*x1 + x2)/3, x1 = S x0, x2 = S x1, S = D^-1/2 A D^-1/2.

#define EMB 64
#define MAX_NODES 200000
#define MAX_DEDGES 2500000
#define SCAN_B 256
#define MAX_SCAN_BLOCKS 1024   // ceil(200000/256) = 782

__device__ int   g_deg[MAX_NODES];
__device__ float g_dis[MAX_NODES];
__device__ int   g_row[MAX_NODES + 1];
__device__ int   g_cursor[MAX_NODES];
__device__ int   g_bsums[MAX_SCAN_BLOCKS];
__device__ int   g_boff[MAX_SCAN_BLOCKS];
__device__ int   g_adj[MAX_DEDGES];
__device__ float g_x1[(size_t)MAX_NODES * EMB];           // fp32 x1 (for combine)
__device__ uint4 g_x0h[(size_t)MAX_NODES * EMB / 8];      // bf16 dis[s]*x0[s]
__device__ uint4 g_x1h[(size_t)MAX_NODES * EMB / 8];      // bf16 dis[s]*x1[s]

__global__ void zero_deg_kernel(int N) {
    int n = blockIdx.x * blockDim.x + threadIdx.x;
    if (n < N) g_deg[n] = 0;
}

__global__ void deg_kernel(const int* __restrict__ u_idx,
                           const int* __restrict__ i_idx,
                           int E, int NU) {
    int e = blockIdx.x * blockDim.x + threadIdx.x;
    if (e < E) {
        atomicAdd(&g_deg[u_idx[e]], 1);
        atomicAdd(&g_deg[NU + i_idx[e]], 1);
    }
}

// ---- prefix scan (exclusive) of g_deg into g_row; also computes g_dis ----

__global__ void scan1_kernel(int N) {
    __shared__ int sh[SCAN_B];
    int t = threadIdx.x;
    int idx = blockIdx.x * SCAN_B + t;
    int v = (idx < N) ? g_deg[idx] : 0;
    if (idx < N) g_dis[idx] = (v > 0) ? rsqrtf((float)v) : 0.0f;
    sh[t] = v;
    __syncthreads();
    for (int off = 1; off < SCAN_B; off <<= 1) {
        int tmp = (t >= off) ? sh[t - off] : 0;
        __syncthreads();
        sh[t] += tmp;
        __syncthreads();
    }
    int incl = sh[t];
    if (idx < N) g_row[idx] = incl - v;   // block-local exclusive
    if (t == SCAN_B - 1) g_bsums[blockIdx.x] = incl;
}

__global__ void scan2_kernel(int nblocks) {
    __shared__ int sh[MAX_SCAN_BLOCKS];
    int t = threadIdx.x;
    int v = (t < nblocks) ? g_bsums[t] : 0;
    sh[t] = v;
    __syncthreads();
    for (int off = 1; off < MAX_SCAN_BLOCKS; off <<= 1) {
        int tmp = (t >= off) ? sh[t - off] : 0;
        __syncthreads();
        sh[t] += tmp;
        __syncthreads();
    }
    if (t < nblocks) g_boff[t] = sh[t] - v;  // exclusive
}

__global__ void scan3_kernel(int N, int twoE) {
    int idx = blockIdx.x * SCAN_B + threadIdx.x;
    if (idx < N) {
        int r = g_row[idx] + g_boff[blockIdx.x];
        g_row[idx] = r;
        g_cursor[idx] = r;
    }
    if (idx == 0) g_row[N] = twoE;
}

__global__ void fill_kernel(const int* __restrict__ u_idx,
                            const int* __restrict__ i_idx,
                            int E, int NU) {
    int e = blockIdx.x * blockDim.x + threadIdx.x;
    if (e < E) {
        int u = u_idx[e];
        int g = NU + i_idx[e];
        g_adj[atomicAdd(&g_cursor[g], 1)] = u;
        g_adj[atomicAdd(&g_cursor[u], 1)] = g;
    }
}

__device__ __forceinline__ uint4 pack8(const float* a, float s) {
    uint4 v;
    __nv_bfloat162* h = reinterpret_cast<__nv_bfloat162*>(&v);
    h[0] = __float22bfloat162_rn(make_float2(s * a[0], s * a[1]));
    h[1] = __float22bfloat162_rn(make_float2(s * a[2], s * a[3]));
    h[2] = __float22bfloat162_rn(make_float2(s * a[4], s * a[5]));
    h[3] = __float22bfloat162_rn(make_float2(s * a[6], s * a[7]));
    return v;
}

__device__ __forceinline__ void accum8(float* acc, uint4 v) {
    __nv_bfloat162* h = reinterpret_cast<__nv_bfloat162*>(&v);
    float2 f0 = __bfloat1622float2(h[0]);
    float2 f1 = __bfloat1622float2(h[1]);
    float2 f2 = __bfloat1622float2(h[2]);
    float2 f3 = __bfloat1622float2(h[3]);
    acc[0] += f0.x; acc[1] += f0.y;
    acc[2] += f1.x; acc[3] += f1.y;
    acc[4] += f2.x; acc[5] += f2.y;
    acc[6] += f3.x; acc[7] += f3.y;
}

// g_x0h[n] = bf16(dis[n] * x0[n]); one uint4 chunk (8 dims) per thread.
__global__ void conv_kernel(const float* __restrict__ u_emb,
                            const float* __restrict__ i_emb,
                            int N, int NU) {
    size_t tot = (size_t)N * 8;
    size_t stride = (size_t)gridDim.x * blockDim.x;
    for (size_t idx = (size_t)blockIdx.x * blockDim.x + threadIdx.x; idx < tot; idx += stride) {
        int row = (int)(idx >> 3);
        int c   = (int)(idx & 7);
        float dn = g_dis[row];
        const float* src = (row < NU) ? (u_emb + (size_t)row * EMB)
                                      : (i_emb + (size_t)(row - NU) * EMB);
        float vals[8];
        float4 a = ((const float4*)src)[c * 2];
        float4 b = ((const float4*)src)[c * 2 + 1];
        vals[0] = a.x; vals[1] = a.y; vals[2] = a.z; vals[3] = a.w;
        vals[4] = b.x; vals[5] = b.y; vals[6] = b.z; vals[7] = b.w;
        g_x0h[idx] = pack8(vals, dn);
    }
}

// ---- pull pass 1: x1 = S x0, sources pre-folded bf16 rows ----
// Warp per node. 8 lanes per row (uint4 = 8 bf16 dims each); 4 neighbors per
// step via lane bits 3-4; unroll x2 -> 8 neighbors, 2 uint4 gathers in flight.
__global__ void pull1_kernel(int N) {
    int warp = (int)(((size_t)blockIdx.x * blockDim.x + threadIdx.x) >> 5);
    int lane = threadIdx.x & 31;
    if (warp >= N) return;

    int off = (lane >> 3) & 3;   // which of 4 neighbors in a step
    int c   = lane & 7;          // uint4 chunk within row

    int start = g_row[warp];
    int end   = g_row[warp + 1];

    float acc[8] = {0.f, 0.f, 0.f, 0.f, 0.f, 0.f, 0.f, 0.f};
    int k = start;

    for (; k + 7 < end; k += 8) {
        int sA = g_adj[k + off];
        int sB = g_adj[k + 4 + off];
        uint4 vA = (g_x0h + (size_t)sA * 8)[c];
        uint4 vB = (g_x0h + (size_t)sB * 8)[c];
        accum8(acc, vA);
        accum8(acc, vB);
    }
    for (; k < end; k += 4) {
        int nbr = k + off;
        if (nbr < end) {
            int s = g_adj[nbr];
            uint4 v = (g_x0h + (size_t)s * 8)[c];
            accum8(acc, v);
        }
    }

    #pragma unroll
    for (int i = 0; i < 8; i++) {
        acc[i] += __shfl_xor_sync(0xffffffffu, acc[i], 8);
        acc[i] += __shfl_xor_sync(0xffffffffu, acc[i], 16);
    }

    if (lane < 8) {
        float dn = g_dis[warp];
        float4 o0 = make_float4(dn * acc[0], dn * acc[1], dn * acc[2], dn * acc[3]);
        float4 o1 = make_float4(dn * acc[4], dn * acc[5], dn * acc[6], dn * acc[7]);
        float4* x1p = (float4*)(g_x1 + (size_t)warp * EMB);
        x1p[c * 2]     = o0;
        x1p[c * 2 + 1] = o1;
        // g_x1h[n] = bf16(dis[n] * x1[n]) = dn^2 * acc
        float x1vals[8] = {o0.x, o0.y, o0.z, o0.w, o1.x, o1.y, o1.z, o1.w};
        (g_x1h + (size_t)warp * 8)[c] = pack8(x1vals, dn);
    }
}

// ---- pull pass 2 fused with output combine ----
// out[n] = (2*x0[n] + 2*x1[n] + dis[n]*sum_s (dis[s]*x1[s])) / 3
__global__ void pull2_kernel(const float* __restrict__ u_emb,
                             const float* __restrict__ i_emb,
                             float* __restrict__ out,
                             int N, int NU) {
    int warp = (int)(((size_t)blockIdx.x * blockDim.x + threadIdx.x) >> 5);
    int lane = threadIdx.x & 31;
    if (warp >= N) return;

    int off = (lane >> 3) & 3;
    int c   = lane & 7;

    int start = g_row[warp];
    int end   = g_row[warp + 1];

    float acc[8] = {0.f, 0.f, 0.f, 0.f, 0.f, 0.f, 0.f, 0.f};
    int k = start;

    for (; k + 7 < end; k += 8) {
        int sA = g_adj[k + off];
        int sB = g_adj[k + 4 + off];
        uint4 vA = (g_x1h + (size_t)sA * 8)[c];
        uint4 vB = (g_x1h + (size_t)sB * 8)[c];
        accum8(acc, vA);
        accum8(acc, vB);
    }
    for (; k < end; k += 4) {
        int nbr = k + off;
        if (nbr < end) {
            int s = g_adj[nbr];
            uint4 v = (g_x1h + (size_t)s * 8)[c];
            accum8(acc, v);
        }
    }

    #pragma unroll
    for (int i = 0; i < 8; i++) {
        acc[i] += __shfl_xor_sync(0xffffffffu, acc[i], 8);
        acc[i] += __shfl_xor_sync(0xffffffffu, acc[i], 16);
    }

    if (lane < 8) {
        float dn = g_dis[warp];
        const float* x0b = (warp < NU) ? (u_emb + (size_t)warp * EMB)
                                       : (i_emb + (size_t)(warp - NU) * EMB);
        float4 x0a = ((const float4*)x0b)[c * 2];
        float4 x0b4 = ((const float4*)x0b)[c * 2 + 1];
        const float4* x1p = (const float4*)(g_x1 + (size_t)warp * EMB);
        float4 x1a = x1p[c * 2];
        float4 x1b = x1p[c * 2 + 1];
        const float inv3 = 1.0f / 3.0f;
        float4 oa, ob;
        oa.x = (2.f * x0a.x + 2.f * x1a.x + dn * acc[0]) * inv3;
        oa.y = (2.f * x0a.y + 2.f * x1a.y + dn * acc[1]) * inv3;
        oa.z = (2.f * x0a.z + 2.f * x1a.z + dn * acc[2]) * inv3;
        oa.w = (2.f * x0a.w + 2.f * x1a.w + dn * acc[3]) * inv3;
        ob.x = (2.f * x0b4.x + 2.f * x1b.x + dn * acc[4]) * inv3;
        ob.y = (2.f * x0b4.y + 2.f * x1b.y + dn * acc[5]) * inv3;
        ob.z = (2.f * x0b4.z + 2.f * x1b.z + dn * acc[6]) * inv3;
        ob.w = (2.f * x0b4.w + 2.f * x1b.w + dn * acc[7]) * inv3;
        float4* op = (float4*)(out + (size_t)warp * EMB);
        op[c * 2]     = oa;
        op[c * 2 + 1] = ob;
    }
}

extern "C" void kernel_launch(void* const* d_in, const int* in_sizes, int n_in,
                              void* d_out, int out_size) {
    const float* u_emb = (const float*)d_in[0];
    const float* i_emb = (const float*)d_in[1];
    const int*   u_idx = (const int*)d_in[2];
    const int*   i_idx = (const int*)d_in[3];
    float*       out   = (float*)d_out;

    int NU = in_sizes[0] / EMB;
    int NI = in_sizes[1] / EMB;
    int E  = in_sizes[2];
    int N  = NU + NI;

    int nScanBlocks = (N + SCAN_B - 1) / SCAN_B;

    zero_deg_kernel<<<(N + 255) / 256, 256>>>(N);
    deg_kernel<<<(E + 255) / 256, 256>>>(u_idx, i_idx, E, NU);

    scan1_kernel<<<nScanBlocks, SCAN_B>>>(N);
    scan2_kernel<<<1, MAX_SCAN_BLOCKS>>>(nScanBlocks);
    scan3_kernel<<<nScanBlocks, SCAN_B>>>(N, 2 * E);

    fill_kernel<<<(E + 255) / 256, 256>>>(u_idx, i_idx, E, NU);
    conv_kernel<<<2048, 256>>>(u_emb, i_emb, N, NU);

    {
        size_t threads_total = (size_t)N * 32;
        int blocks = (int)((threads_total + 255) / 256);
        pull1_kernel<<<blocks, 256>>>(N);
        pull2_kernel<<<blocks, 256>>>(u_emb, i_emb, out, N, NU);
    }
}

// round 8
// speedup vs baseline: 1.1522x; 1.1522x over previous
#include <cuda_runtime.h>
#include <cstdint>

// LightGCN 2-hop smoothing, pull-based SpMM over an on-the-fly CSR.
// fp32 throughout. Uniform predicated gather loop (MLP=4, no serial tail).
// out = (2*x0 + 2*x1 + x2)/3, x1 = S x0, x2 = S x1, S = D^-1/2 A D^-1/2.

#define EMB 64
#define MAX_NODES 200000
#define MAX_DEDGES 2500000
#define SCAN_B 256
#define MAX_SCAN_BLOCKS 1024   // ceil(200000/256) = 782

__device__ int   g_deg[MAX_NODES];
__device__ float g_dis[MAX_NODES];
__device__ int   g_row[MAX_NODES + 1];
__device__ int   g_cursor[MAX_NODES];
__device__ int   g_bsums[MAX_SCAN_BLOCKS];
__device__ int   g_boff[MAX_SCAN_BLOCKS];
__device__ int   g_adj[MAX_DEDGES];
__device__ float g_x1[(size_t)MAX_NODES * EMB];

__global__ void zero_deg_kernel(int N) {
    int n = blockIdx.x * blockDim.x + threadIdx.x;
    if (n < N) g_deg[n] = 0;
}

__global__ void deg_kernel(const int* __restrict__ u_idx,
                           const int* __restrict__ i_idx,
                           int E, int NU) {
    int e = blockIdx.x * blockDim.x + threadIdx.x;
    if (e < E) {
        atomicAdd(&g_deg[u_idx[e]], 1);
        atomicAdd(&g_deg[NU + i_idx[e]], 1);
    }
}

// ---- scan1: block-local exclusive scan of g_deg into g_row (shfl-based) ----
__global__ void scan1_kernel(int N) {
    __shared__ int warp_tot[SCAN_B / 32];
    int t = threadIdx.x;
    int lane = t & 31;
    int wid = t >> 5;
    int idx = blockIdx.x * SCAN_B + t;
    int v = (idx < N) ? g_deg[idx] : 0;
    if (idx < N) g_dis[idx] = (v > 0) ? rsqrtf((float)v) : 0.0f;

    // inclusive warp scan
    int s = v;
    #pragma unroll
    for (int off = 1; off < 32; off <<= 1) {
        int n = __shfl_up_sync(0xffffffffu, s, off);
        if (lane >= off) s += n;
    }
    if (lane == 31) warp_tot[wid] = s;
    __syncthreads();
    if (wid == 0) {
        // FULL warp participates in the shfl; only lanes < nwarps carry data.
        int w = (lane < SCAN_B / 32) ? warp_tot[lane] : 0;
        #pragma unroll
        for (int off = 1; off < 32; off <<= 1) {
            int n = __shfl_up_sync(0xffffffffu, w, off);
            if (lane >= off) w += n;
        }
        if (lane < SCAN_B / 32) warp_tot[lane] = w;
    }
    __syncthreads();
    int base = (wid > 0) ? warp_tot[wid - 1] : 0;
    int incl = base + s;
    if (idx < N) g_row[idx] = incl - v;           // block-local exclusive
    if (t == SCAN_B - 1) g_bsums[blockIdx.x] = incl;
}

// ---- scan2: exclusive scan of block sums (<=1024), shfl-based ----
__global__ void scan2_kernel(int nblocks) {
    __shared__ int warp_tot[32];
    int t = threadIdx.x;
    int lane = t & 31;
    int wid = t >> 5;
    int v = (t < nblocks) ? g_bsums[t] : 0;
    int s = v;
    #pragma unroll
    for (int off = 1; off < 32; off <<= 1) {
        int n = __shfl_up_sync(0xffffffffu, s, off);
        if (lane >= off) s += n;
    }
    if (lane == 31) warp_tot[wid] = s;
    __syncthreads();
    if (wid == 0) {
        int w = warp_tot[lane];   // block is exactly 1024 threads -> 32 warps
        #pragma unroll
        for (int off = 1; off < 32; off <<= 1) {
            int n = __shfl_up_sync(0xffffffffu, w, off);
            if (lane >= off) w += n;
        }
        warp_tot[lane] = w;
    }
    __syncthreads();
    int base = (wid > 0) ? warp_tot[wid - 1] : 0;
    if (t < nblocks) g_boff[t] = base + s - v;    // exclusive
}

__global__ void scan3_kernel(int N, int twoE) {
    int idx = blockIdx.x * SCAN_B + threadIdx.x;
    if (idx < N) {
        int r = g_row[idx] + g_boff[blockIdx.x];
        g_row[idx] = r;
        g_cursor[idx] = r;
    }
    if (idx == 0) g_row[N] = twoE;
}

__global__ void fill_kernel(const int* __restrict__ u_idx,
                            const int* __restrict__ i_idx,
                            int E, int NU) {
    int e = blockIdx.x * blockDim.x + threadIdx.x;
    if (e < E) {
        int u = u_idx[e];
        int g = NU + i_idx[e];
        g_adj[atomicAdd(&g_cursor[g], 1)] = u;
        g_adj[atomicAdd(&g_cursor[u], 1)] = g;
    }
}

// ---- pull pass 1: x1 = S x0 ----
// Warp per node. Half-warps (16 lanes, float4 each = 256B row) take alternate
// neighbor slots. Uniform loop: 8 slots/step, indices clamped, weights zeroed
// when out of range -> MLP=4 every step, no serial tail.
__global__ void pull1_kernel(const float* __restrict__ u_emb,
                             const float* __restrict__ i_emb,
                             int N, int NU) {
    int warp = (int)(((size_t)blockIdx.x * blockDim.x + threadIdx.x) >> 5);
    int lane = threadIdx.x & 31;
    if (warp >= N) return;

    int half = lane >> 4;
    int q    = lane & 15;

    int start = g_row[warp];
    int end   = g_row[warp + 1];

    float4 acc = make_float4(0.f, 0.f, 0.f, 0.f);

    for (int k = start; k < end; k += 8) {
        int i0 = k + half, i1 = k + 2 + half, i2 = k + 4 + half, i3 = k + 6 + half;
        int lim = end - 1;
        int s0 = g_adj[min(i0, lim)];
        int s1 = g_adj[min(i1, lim)];
        int s2 = g_adj[min(i2, lim)];
        int s3 = g_adj[min(i3, lim)];
        float w0 = (i0 < end) ? g_dis[s0] : 0.f;
        float w1 = (i1 < end) ? g_dis[s1] : 0.f;
        float w2 = (i2 < end) ? g_dis[s2] : 0.f;
        float w3 = (i3 < end) ? g_dis[s3] : 0.f;
        const float4* p0 = (s0 < NU) ? (const float4*)(u_emb + (size_t)s0 * EMB)
                                     : (const float4*)(i_emb + (size_t)(s0 - NU) * EMB);
        const float4* p1 = (s1 < NU) ? (const float4*)(u_emb + (size_t)s1 * EMB)
                                     : (const float4*)(i_emb + (size_t)(s1 - NU) * EMB);
        const float4* p2 = (s2 < NU) ? (const float4*)(u_emb + (size_t)s2 * EMB)
                                     : (const float4*)(i_emb + (size_t)(s2 - NU) * EMB);
        const float4* p3 = (s3 < NU) ? (const float4*)(u_emb + (size_t)s3 * EMB)
                                     : (const float4*)(i_emb + (size_t)(s3 - NU) * EMB);
        float4 v0 = p0[q], v1 = p1[q], v2 = p2[q], v3 = p3[q];
        acc.x += w0 * v0.x + w1 * v1.x + w2 * v2.x + w3 * v3.x;
        acc.y += w0 * v0.y + w1 * v1.y + w2 * v2.y + w3 * v3.y;
        acc.z += w0 * v0.z + w1 * v1.z + w2 * v2.z + w3 * v3.z;
        acc.w += w0 * v0.w + w1 * v1.w + w2 * v2.w + w3 * v3.w;
    }

    acc.x += __shfl_xor_sync(0xffffffffu, acc.x, 16);
    acc.y += __shfl_xor_sync(0xffffffffu, acc.y, 16);
    acc.z += __shfl_xor_sync(0xffffffffu, acc.z, 16);
    acc.w += __shfl_xor_sync(0xffffffffu, acc.w, 16);

    if (half == 0) {
        float dn = g_dis[warp];
        ((float4*)(g_x1 + (size_t)warp * EMB))[q] =
            make_float4(dn * acc.x, dn * acc.y, dn * acc.z, dn * acc.w);
    }
}

// ---- pull pass 2 fused with output combine ----
// out[n] = (2*x0[n] + 2*x1[n] + dis[n]*sum dis[s]*x1[s]) / 3
__global__ void pull2_kernel(const float* __restrict__ u_emb,
                             const float* __restrict__ i_emb,
                             float* __restrict__ out,
                             int N, int NU) {
    int warp = (int)(((size_t)blockIdx.x * blockDim.x + threadIdx.x) >> 5);
    int lane = threadIdx.x & 31;
    if (warp >= N) return;

    int half = lane >> 4;
    int q    = lane & 15;

    int start = g_row[warp];
    int end   = g_row[warp + 1];

    float4 acc = make_float4(0.f, 0.f, 0.f, 0.f);

    for (int k = start; k < end; k += 8) {
        int i0 = k + half, i1 = k + 2 + half, i2 = k + 4 + half, i3 = k + 6 + half;
        int lim = end - 1;
        int s0 = g_adj[min(i0, lim)];
        int s1 = g_adj[min(i1, lim)];
        int s2 = g_adj[min(i2, lim)];
        int s3 = g_adj[min(i3, lim)];
        float w0 = (i0 < end) ? g_dis[s0] : 0.f;
        float w1 = (i1 < end) ? g_dis[s1] : 0.f;
        float w2 = (i2 < end) ? g_dis[s2] : 0.f;
        float w3 = (i3 < end) ? g_dis[s3] : 0.f;
        float4 v0 = ((const float4*)(g_x1 + (size_t)s0 * EMB))[q];
        float4 v1 = ((const float4*)(g_x1 + (size_t)s1 * EMB))[q];
        float4 v2 = ((const float4*)(g_x1 + (size_t)s2 * EMB))[q];
        float4 v3 = ((const float4*)(g_x1 + (size_t)s3 * EMB))[q];
        acc.x += w0 * v0.x + w1 * v1.x + w2 * v2.x + w3 * v3.x;
        acc.y += w0 * v0.y + w1 * v1.y + w2 * v2.y + w3 * v3.y;
        acc.z += w0 * v0.z + w1 * v1.z + w2 * v2.z + w3 * v3.z;
        acc.w += w0 * v0.w + w1 * v1.w + w2 * v2.w + w3 * v3.w;
    }

    acc.x += __shfl_xor_sync(0xffffffffu, acc.x, 16);
    acc.y += __shfl_xor_sync(0xffffffffu, acc.y, 16);
    acc.z += __shfl_xor_sync(0xffffffffu, acc.z, 16);
    acc.w += __shfl_xor_sync(0xffffffffu, acc.w, 16);

    if (half == 0) {
        float dn = g_dis[warp];
        const float4* x0b = (warp < NU)
            ? (const float4*)(u_emb + (size_t)warp * EMB)
            : (const float4*)(i_emb + (size_t)(warp - NU) * EMB);
        float4 x0v = x0b[q];
        float4 x1v = ((const float4*)(g_x1 + (size_t)warp * EMB))[q];
        const float inv3 = 1.0f / 3.0f;
        float4 o;
        o.x = (2.0f * x0v.x + 2.0f * x1v.x + dn * acc.x) * inv3;
        o.y = (2.0f * x0v.y + 2.0f * x1v.y + dn * acc.y) * inv3;
        o.z = (2.0f * x0v.z + 2.0f * x1v.z + dn * acc.z) * inv3;
        o.w = (2.0f * x0v.w + 2.0f * x1v.w + dn * acc.w) * inv3;
        ((float4*)(out + (size_t)warp * EMB))[q] = o;
    }
}

extern "C" void kernel_launch(void* const* d_in, const int* in_sizes, int n_in,
                              void* d_out, int out_size) {
    const float* u_emb = (const float*)d_in[0];
    const float* i_emb = (const float*)d_in[1];
    const int*   u_idx = (const int*)d_in[2];
    const int*   i_idx = (const int*)d_in[3];
    float*       out   = (float*)d_out;

    int NU = in_sizes[0] / EMB;
    int NI = in_sizes[1] / EMB;
    int E  = in_sizes[2];
    int N  = NU + NI;

    int nScanBlocks = (N + SCAN_B - 1) / SCAN_B;

    zero_deg_kernel<<<(N + 255) / 256, 256>>>(N);
    deg_kernel<<<(E + 255) / 256, 256>>>(u_idx, i_idx, E, NU);

    scan1_kernel<<<nScanBlocks, SCAN_B>>>(N);
    scan2_kernel<<<1, 1024>>>(nScanBlocks);
    scan3_kernel<<<nScanBlocks, SCAN_B>>>(N, 2 * E);

    fill_kernel<<<(E + 255) / 256, 256>>>(u_idx, i_idx, E, NU);

    {
        size_t threads_total = (size_t)N * 32;
        int blocks = (int)((threads_total + 255) / 256);
        pull1_kernel<<<blocks, 256>>>(u_emb, i_emb, N, NU);
        pull2_kernel<<<blocks, 256>>>(u_emb, i_emb, out, N, NU);
    }
}